// round 15
// baseline (speedup 1.0000x reference)
#include <cuda_runtime.h>
#include <cuda_bf16.h>
#include <cstdint>

#define KDIM   256
#define NF     64
#define N1R    8192
#define KH     5
#define BM     32
#define CK     64               // K chunk
#define NCHUNK (KDIM / CK)      // 4
#define NTHR   256

// dynamic smem layout (bytes); strides in bf16 elements
#define BSTRIDE 264             // [n][k] rows: 528B, 16B-aligned, conflict-free ldsm
#define ASTRIDE 72
#define OFF_BHI 0               // 64*264*2      = 33792
#define OFF_BLO 33792
#define OFF_A   67584           // 2 bufs x (Ahi 4608 + Alo 4608)
#define OFF_QS  86016
#define SM_TOTAL 86656

static __device__ __forceinline__ uint32_t smem_cast(const void* p) {
    return (uint32_t)__cvta_generic_to_shared(p);
}
static __device__ __forceinline__ void ldsm_x4(uint32_t* r, uint32_t addr) {
    asm volatile("ldmatrix.sync.aligned.m8n8.x4.shared.b16 {%0,%1,%2,%3}, [%4];"
                 : "=r"(r[0]), "=r"(r[1]), "=r"(r[2]), "=r"(r[3]) : "r"(addr));
}
static __device__ __forceinline__ void mma_bf16(float* d, const uint32_t* a,
                                                uint32_t b0, uint32_t b1) {
    asm volatile("mma.sync.aligned.m16n8k16.row.col.f32.bf16.bf16.f32 "
                 "{%0,%1,%2,%3}, {%4,%5,%6,%7}, {%8,%9}, {%0,%1,%2,%3};"
                 : "+f"(d[0]), "+f"(d[1]), "+f"(d[2]), "+f"(d[3])
                 : "r"(a[0]), "r"(a[1]), "r"(a[2]), "r"(a[3]), "r"(b0), "r"(b1));
}

// ---------------------------------------------------------------------------
// SINGLE fused kernel: out = G @ x @ W + 5*bias
// (floor(softmax/1000) == 0 identically => e == G; G rows = 5 ones at qq.)
// s = gather-sum of x rows (fp32) -> Markidis bf16 split -> HMMA (3 passes:
// hi*hi + hi*lo + lo*hi, fp32 accum).
//
// R14 lesson: B (= W) staging was redundant per-chunk work, and 2 bars/chunk.
// Here: B split hi/lo ONCE into full-K smem [n][k] (n-major, non-trans ldsm
// gives identical fragments to the validated [k][n]+trans layout), and A is
// double-buffered so each chunk needs only ONE barrier:
//   conv A(c)->buf[c&1]; bar; issue A(c+1); mma(c)
// (bar(c+1) orders all ldsm(c) reads before conv(c+2) rewrites buf[c&1]).
// 84.6KB dynamic smem -> 2 CTAs/SM, 16 warps/SM; regs ~105 (B prefetch gone).
// ---------------------------------------------------------------------------
__global__ __launch_bounds__(NTHR, 2) void fused_tc_kernel(const float* __restrict__ x,
                                                           const int* __restrict__ qq,
                                                           const float* __restrict__ w,
                                                           const float* __restrict__ bias,
                                                           float* __restrict__ out) {
    extern __shared__ char sm[];
    __nv_bfloat16* Bhi = (__nv_bfloat16*)(sm + OFF_BHI);
    __nv_bfloat16* Blo = (__nv_bfloat16*)(sm + OFF_BLO);
    int* qs = (int*)(sm + OFF_QS);

    const int tid  = threadIdx.x;
    const int wid  = tid >> 5;
    const int lane = tid & 31;
    const int r0   = blockIdx.x * BM;
    const int m0   = (wid & 1) * 16;
    const int n0   = (wid >> 1) * 16;

    for (int t = tid; t < BM * KH; t += NTHR) qs[t] = qq[r0 * KH + t];
    __syncthreads();

    const float4* x4 = (const float4*)x;   // row stride 64 float4
    const float4* w4 = (const float4*)w;   // row stride 16 float4

    // per-thread A staging coords + cached q indices
    int arow[2], ac4[2], qi[2][KH];
    #pragma unroll
    for (int j = 0; j < 2; j++) {
        int idx = tid + j * NTHR;          // 0..511
        arow[j] = idx >> 4; ac4[j] = idx & 15;
        #pragma unroll
        for (int t = 0; t < KH; t++) qi[j][t] = qs[arow[j] * KH + t];
    }

    float4 pa[2][KH];
    float  d[2][4] = {};

#define ISSUE(c)                                                               \
    {                                                                          \
        _Pragma("unroll")                                                      \
        for (int j = 0; j < 2; j++) {                                          \
            const float4* xp = x4 + (c) * 16 + ac4[j];                         \
            _Pragma("unroll")                                                  \
            for (int t = 0; t < KH; t++) pa[j][t] = xp[(size_t)qi[j][t] * 64]; \
        }                                                                      \
    }

    ISSUE(0);   // gather latency overlaps the one-time B build below

    // ---- build B = W split hi/lo, [n][k] n-major, ONCE ----
    #pragma unroll
    for (int j = 0; j < 8; j++) {
        int idx = tid + j * NTHR;          // 0..2047
        int kp = idx >> 4;                 // k-pair 0..127
        int c4 = idx & 15;
        float4 v0 = w4[(size_t)(2 * kp + 0) * 16 + c4];
        float4 v1 = w4[(size_t)(2 * kp + 1) * 16 + c4];
        const float e0[4] = {v0.x, v0.y, v0.z, v0.w};
        const float e1[4] = {v1.x, v1.y, v1.z, v1.w};
        #pragma unroll
        for (int e = 0; e < 4; e++) {
            int n = c4 * 4 + e;
            float h0 = __bfloat162float(__float2bfloat16_rn(e0[e]));
            float h1 = __bfloat162float(__float2bfloat16_rn(e1[e]));
            *(__nv_bfloat162*)&Bhi[n * BSTRIDE + 2 * kp] = __floats2bfloat162_rn(h0, h1);
            *(__nv_bfloat162*)&Blo[n * BSTRIDE + 2 * kp] =
                __floats2bfloat162_rn(e0[e] - h0, e1[e] - h1);
        }
    }

    const int a_row = m0 + (lane & 15);
    const int a_col = (lane >> 4) << 3;
    const int b_n   = n0 + (lane & 7) + ((lane & 16) >> 1);
    const int b_k   = lane & 8;

    #pragma unroll 1
    for (int c = 0; c < NCHUNK; c++) {
        __nv_bfloat16* Ahi = (__nv_bfloat16*)(sm + OFF_A + (c & 1) * 9216);
        __nv_bfloat16* Alo = Ahi + 2304;   // 4608 bytes

        // ---- convert prefetched gathers -> A tiles (buf c&1) ----
        #pragma unroll
        for (int j = 0; j < 2; j++) {
            float sx = pa[j][0].x + pa[j][1].x + pa[j][2].x + pa[j][3].x + pa[j][4].x;
            float sy = pa[j][0].y + pa[j][1].y + pa[j][2].y + pa[j][3].y + pa[j][4].y;
            float sz = pa[j][0].z + pa[j][1].z + pa[j][2].z + pa[j][3].z + pa[j][4].z;
            float sw = pa[j][0].w + pa[j][1].w + pa[j][2].w + pa[j][3].w + pa[j][4].w;
            float hx = __bfloat162float(__float2bfloat16_rn(sx));
            float hy = __bfloat162float(__float2bfloat16_rn(sy));
            float hz = __bfloat162float(__float2bfloat16_rn(sz));
            float hw = __bfloat162float(__float2bfloat16_rn(sw));
            int base = arow[j] * ASTRIDE + ac4[j] * 4;
            *(__nv_bfloat162*)&Ahi[base + 0] = __floats2bfloat162_rn(hx, hy);
            *(__nv_bfloat162*)&Ahi[base + 2] = __floats2bfloat162_rn(hz, hw);
            *(__nv_bfloat162*)&Alo[base + 0] = __floats2bfloat162_rn(sx - hx, sy - hy);
            *(__nv_bfloat162*)&Alo[base + 2] = __floats2bfloat162_rn(sz - hz, sw - hw);
        }
        __syncthreads();                   // the ONLY barrier per chunk
                                           // (also orders B build before mma at c=0)

        if (c < NCHUNK - 1) ISSUE(c + 1);  // overlap next gathers with mma

        // ---- mma: 4 k16 steps, warp tile m16 x n16 ----
        #pragma unroll
        for (int ko = 0; ko < CK; ko += 16) {
            const int kg = c * CK + ko + b_k;
            uint32_t ah[4], al[4], bh[4], bl[4];
            ldsm_x4(ah, smem_cast(&Ahi[a_row * ASTRIDE + ko + a_col]));
            ldsm_x4(al, smem_cast(&Alo[a_row * ASTRIDE + ko + a_col]));
            ldsm_x4(bh, smem_cast(&Bhi[b_n * BSTRIDE + kg]));
            ldsm_x4(bl, smem_cast(&Blo[b_n * BSTRIDE + kg]));
            mma_bf16(d[0], ah, bh[0], bh[1]);   // hi*hi
            mma_bf16(d[1], ah, bh[2], bh[3]);
            mma_bf16(d[0], ah, bl[0], bl[1]);   // hi*lo
            mma_bf16(d[1], ah, bl[2], bl[3]);
            mma_bf16(d[0], al, bh[0], bh[1]);   // lo*hi
            mma_bf16(d[1], al, bh[2], bh[3]);
        }
    }
#undef ISSUE

    // ---- epilogue: frag -> out with + 5*bias ----
    const int fr  = lane >> 2;
    const int fc2 = (lane & 3) * 2;
    #pragma unroll
    for (int n8 = 0; n8 < 2; n8++) {
        int col = n0 + n8 * 8 + fc2;
        float2 bv = *(const float2*)&bias[col];
        int rowA = r0 + m0 + fr;
        int rowB = rowA + 8;
        *(float2*)&out[(size_t)rowA * NF + col] =
            make_float2(d[n8][0] + 5.0f * bv.x, d[n8][1] + 5.0f * bv.y);
        *(float2*)&out[(size_t)rowB * NF + col] =
            make_float2(d[n8][2] + 5.0f * bv.x, d[n8][3] + 5.0f * bv.y);
    }
}

// ---------------------------------------------------------------------------
// Inputs (metadata order):
//   0: x [10000,256] f32, 1: G (unused), 2: weight [256,64] f32,
//   3: a (unused — attention branch identically zero), 4: bias [64] f32,
//   5: qq [40960] i32, 6: rows (unused)
// output: [8192,64] f32
// ---------------------------------------------------------------------------
extern "C" void kernel_launch(void* const* d_in, const int* in_sizes, int n_in,
                              void* d_out, int out_size) {
    const float* x    = (const float*)d_in[0];
    const float* w    = (const float*)d_in[2];
    const float* bias = (const float*)d_in[4];
    const int*   qq   = (const int*)d_in[5];
    float*       out  = (float*)d_out;

    cudaFuncSetAttribute(fused_tc_kernel,
                         cudaFuncAttributeMaxDynamicSharedMemorySize, SM_TOTAL);
    fused_tc_kernel<<<N1R / BM, NTHR, SM_TOTAL>>>(x, qq, w, bias, out);
}

// round 16
// speedup vs baseline: 1.0889x; 1.0889x over previous
#include <cuda_runtime.h>
#include <cuda_bf16.h>
#include <cstdint>

#define KDIM   256
#define NF     64
#define N1R    8192
#define KH     5
#define BM     32
#define CK     64               // K chunk
#define NCHUNK (KDIM / CK)      // 4
#define NTHR   256

static __device__ __forceinline__ uint32_t smem_cast(const void* p) {
    return (uint32_t)__cvta_generic_to_shared(p);
}
static __device__ __forceinline__ void ldsm_x4(uint32_t* r, uint32_t addr) {
    asm volatile("ldmatrix.sync.aligned.m8n8.x4.shared.b16 {%0,%1,%2,%3}, [%4];"
                 : "=r"(r[0]), "=r"(r[1]), "=r"(r[2]), "=r"(r[3]) : "r"(addr));
}
static __device__ __forceinline__ void ldsm_x4_t(uint32_t* r, uint32_t addr) {
    asm volatile("ldmatrix.sync.aligned.m8n8.x4.trans.shared.b16 {%0,%1,%2,%3}, [%4];"
                 : "=r"(r[0]), "=r"(r[1]), "=r"(r[2]), "=r"(r[3]) : "r"(addr));
}
static __device__ __forceinline__ void mma_bf16(float* d, const uint32_t* a,
                                                uint32_t b0, uint32_t b1) {
    asm volatile("mma.sync.aligned.m16n8k16.row.col.f32.bf16.bf16.f32 "
                 "{%0,%1,%2,%3}, {%4,%5,%6,%7}, {%8,%9}, {%0,%1,%2,%3};"
                 : "+f"(d[0]), "+f"(d[1]), "+f"(d[2]), "+f"(d[3])
                 : "r"(a[0]), "r"(a[1]), "r"(a[2]), "r"(a[3]), "r"(b0), "r"(b1));
}

// ---------------------------------------------------------------------------
// SINGLE fused kernel: out = G @ x @ W + 5*bias
// (floor(softmax/1000) == 0 identically => e == G; G rows = 5 ones at qq.)
// s = gather-sum of x rows (fp32) -> Markidis bf16 split -> HMMA (3 passes:
// hi*hi + hi*lo + lo*hi, fp32 accum; rel ~4e-6).
//
// EXACT R14 structure (best: 12.8us) with ONE lever changed: register diet
// to unlock 3 CTAs/SM. R14 was occ-pinned at 2 CTAs/SM by regs=128 (pa 40 +
// pb 16 + qi 10). Dropped: pb prefetch (W is L1-resident after chunk 0; a
// ~40cy L1-hit load inside the convert phase hides at 24 warps/SM) and the
// qi register cache (re-read from smem qs per chunk). Kept: pa prefetch --
// the long-latency L2 gathers that R14 proved must overlap mma.
// __launch_bounds__(256,3): <=84 regs, 3 CTAs/SM, 24 warps/SM.
// ---------------------------------------------------------------------------
__global__ __launch_bounds__(NTHR, 3) void fused_tc_kernel(const float* __restrict__ x,
                                                           const int* __restrict__ qq,
                                                           const float* __restrict__ w,
                                                           const float* __restrict__ bias,
                                                           float* __restrict__ out) {
    __shared__ __nv_bfloat16 Ahi[BM][72], Alo[BM][72];   // s chunk [32 x 64]
    __shared__ __nv_bfloat16 Bhi[CK][72], Blo[CK][72];   // W chunk [64 x 64]
    __shared__ int qs[BM * KH];

    const int tid  = threadIdx.x;
    const int wid  = tid >> 5;
    const int lane = tid & 31;
    const int r0   = blockIdx.x * BM;
    const int m0   = (wid & 1) * 16;
    const int n0   = (wid >> 1) * 16;

    for (int t = tid; t < BM * KH; t += NTHR) qs[t] = qq[r0 * KH + t];
    __syncthreads();

    const float4* x4 = (const float4*)x;   // row stride 64 float4
    const float4* w4 = (const float4*)w;   // row stride 16 float4

    // per-thread A staging coords (indices re-read from smem each chunk)
    const int arow0 = tid >> 4,  ac40 = tid & 15;          // j = 0
    const int arow1 = arow0 + 16;                          // j = 1 (same c4)

    float4 pa[2][KH];
    float  d[2][4] = {};

    const int a_row = m0 + (lane & 15);
    const int a_col = (lane >> 4) << 3;
    const int b_row = (lane & 7) + (lane & 8);
    const int b_col = (lane >> 4) << 3;

#define ISSUE(c)                                                               \
    {                                                                          \
        const float4* xp = x4 + (c) * 16 + ac40;                               \
        const int* q0 = &qs[arow0 * KH];                                       \
        const int* q1 = &qs[arow1 * KH];                                       \
        _Pragma("unroll")                                                      \
        for (int t = 0; t < KH; t++) pa[0][t] = xp[(size_t)q0[t] * 64];        \
        _Pragma("unroll")                                                      \
        for (int t = 0; t < KH; t++) pa[1][t] = xp[(size_t)q1[t] * 64];        \
    }

    ISSUE(0);

    #pragma unroll 1
    for (int c = 0; c < NCHUNK; c++) {
        // ---- convert prefetched gathers -> A tiles ----
        {
            const int rows[2] = {arow0, arow1};
            #pragma unroll
            for (int j = 0; j < 2; j++) {
                float sx = pa[j][0].x + pa[j][1].x + pa[j][2].x + pa[j][3].x + pa[j][4].x;
                float sy = pa[j][0].y + pa[j][1].y + pa[j][2].y + pa[j][3].y + pa[j][4].y;
                float sz = pa[j][0].z + pa[j][1].z + pa[j][2].z + pa[j][3].z + pa[j][4].z;
                float sw = pa[j][0].w + pa[j][1].w + pa[j][2].w + pa[j][3].w + pa[j][4].w;
                float hx = __bfloat162float(__float2bfloat16_rn(sx));
                float hy = __bfloat162float(__float2bfloat16_rn(sy));
                float hz = __bfloat162float(__float2bfloat16_rn(sz));
                float hw = __bfloat162float(__float2bfloat16_rn(sw));
                int row = rows[j];
                *(__nv_bfloat162*)&Ahi[row][ac40 * 4 + 0] = __floats2bfloat162_rn(hx, hy);
                *(__nv_bfloat162*)&Ahi[row][ac40 * 4 + 2] = __floats2bfloat162_rn(hz, hw);
                *(__nv_bfloat162*)&Alo[row][ac40 * 4 + 0] = __floats2bfloat162_rn(sx - hx, sy - hy);
                *(__nv_bfloat162*)&Alo[row][ac40 * 4 + 2] = __floats2bfloat162_rn(sz - hz, sw - hw);
            }
        }
        // ---- stage B chunk directly (W: L1-resident after chunk 0) ----
        #pragma unroll
        for (int j = 0; j < 4; j++) {
            int idx = tid + j * NTHR;              // 0..1023
            int kk = idx >> 4, c4 = idx & 15;
            float4 v = w4[(size_t)(c * CK + kk) * 16 + c4];
            float hx = __bfloat162float(__float2bfloat16_rn(v.x));
            float hy = __bfloat162float(__float2bfloat16_rn(v.y));
            float hz = __bfloat162float(__float2bfloat16_rn(v.z));
            float hw = __bfloat162float(__float2bfloat16_rn(v.w));
            *(__nv_bfloat162*)&Bhi[kk][c4 * 4 + 0] = __floats2bfloat162_rn(hx, hy);
            *(__nv_bfloat162*)&Bhi[kk][c4 * 4 + 2] = __floats2bfloat162_rn(hz, hw);
            *(__nv_bfloat162*)&Blo[kk][c4 * 4 + 0] = __floats2bfloat162_rn(v.x - hx, v.y - hy);
            *(__nv_bfloat162*)&Blo[kk][c4 * 4 + 2] = __floats2bfloat162_rn(v.z - hz, v.w - hw);
        }
        __syncthreads();

        // ---- prefetch next chunk's gathers: latency overlaps mma ----
        if (c < NCHUNK - 1) ISSUE(c + 1);

        // ---- mma: 4 k16 steps, warp tile m16 x n16 ----
        #pragma unroll
        for (int ko = 0; ko < CK; ko += 16) {
            uint32_t ah[4], al[4], bh[4], bl[4];
            ldsm_x4(ah, smem_cast(&Ahi[a_row][ko + a_col]));
            ldsm_x4(al, smem_cast(&Alo[a_row][ko + a_col]));
            ldsm_x4_t(bh, smem_cast(&Bhi[ko + b_row][n0 + b_col]));
            ldsm_x4_t(bl, smem_cast(&Blo[ko + b_row][n0 + b_col]));
            mma_bf16(d[0], ah, bh[0], bh[1]);   // hi*hi
            mma_bf16(d[1], ah, bh[2], bh[3]);
            mma_bf16(d[0], ah, bl[0], bl[1]);   // hi*lo
            mma_bf16(d[1], ah, bl[2], bl[3]);
            mma_bf16(d[0], al, bh[0], bh[1]);   // lo*hi
            mma_bf16(d[1], al, bh[2], bh[3]);
        }
        __syncthreads();
    }
#undef ISSUE

    // ---- epilogue: frag -> out with + 5*bias ----
    const int fr  = lane >> 2;
    const int fc2 = (lane & 3) * 2;
    #pragma unroll
    for (int n8 = 0; n8 < 2; n8++) {
        int col = n0 + n8 * 8 + fc2;
        float2 bv = *(const float2*)&bias[col];
        int rowA = r0 + m0 + fr;
        int rowB = rowA + 8;
        *(float2*)&out[(size_t)rowA * NF + col] =
            make_float2(d[n8][0] + 5.0f * bv.x, d[n8][1] + 5.0f * bv.y);
        *(float2*)&out[(size_t)rowB * NF + col] =
            make_float2(d[n8][2] + 5.0f * bv.x, d[n8][3] + 5.0f * bv.y);
    }
}

// ---------------------------------------------------------------------------
// Inputs (metadata order):
//   0: x [10000,256] f32, 1: G (unused), 2: weight [256,64] f32,
//   3: a (unused — attention branch identically zero), 4: bias [64] f32,
//   5: qq [40960] i32, 6: rows (unused)
// output: [8192,64] f32
// ---------------------------------------------------------------------------
extern "C" void kernel_launch(void* const* d_in, const int* in_sizes, int n_in,
                              void* d_out, int out_size) {
    const float* x    = (const float*)d_in[0];
    const float* w    = (const float*)d_in[2];
    const float* bias = (const float*)d_in[4];
    const int*   qq   = (const int*)d_in[5];
    float*       out  = (float*)d_out;

    fused_tc_kernel<<<N1R / BM, NTHR>>>(x, qq, w, bias, out);
}